// round 12
// baseline (speedup 1.0000x reference)
#include <cuda_runtime.h>
#include <cuda_bf16.h>
#include <math.h>

#define Bq 512
#define Nq 101
#define Hq 128
#define Tq 140
#define NP 104

// __device__ scratch
__device__ float g_Wfw [129 * 128];                 // Wfc @ Ww
__device__ float g_Wpk2[128 * 128];                 // Wpk @ Wat^T   [k][o]
__device__ float g_poolW[(size_t)Bq * Tq * 128];    // pool@Wfc1^(s+1)@Ww [b][s][:]
__device__ float g_G [(size_t)Bq * Nq * 128];       // enc@Wfw[:128]      [b][n][:]
__device__ float g_V2[(size_t)Bq * 128 * 104];      // V^T  [b][o][m]
__device__ float g_K2[(size_t)Bq * 128 * 104];      // Kp2^T[b][o][n]

// ---------------------------------------------------------------------------
// precomp1: blocks 0..256 fold weights; blocks 257.. pool chains (2 rows each)
// ---------------------------------------------------------------------------
__global__ __launch_bounds__(256)
void precomp1(const float* __restrict__ Wfc, const float* __restrict__ Ww,
              const float* __restrict__ Wat, const float* __restrict__ Wpk,
              const float* __restrict__ pool, const float* __restrict__ Wfc1) {
    const int t = threadIdx.x, bid = blockIdx.x;
    if (bid < 257) {
        __shared__ __align__(16) float row[128];
        if (t < 128) {
            if (bid < 129) row[t] = Wfc[bid * 128 + t];
            else           row[t] = Wpk[(bid - 129) * 128 + t];
        }
        __syncthreads();
        if (t < 128) {
            const float4* r4 = (const float4*)row;
            if (bid < 129) {
                float a = 0.f;
                for (int k4 = 0; k4 < 32; k4++) {
                    float4 r = r4[k4];
                    a += r.x * Ww[(4*k4+0)*128 + t] + r.y * Ww[(4*k4+1)*128 + t]
                       + r.z * Ww[(4*k4+2)*128 + t] + r.w * Ww[(4*k4+3)*128 + t];
                }
                g_Wfw[bid * 128 + t] = a;
            } else {
                const float4* w4 = (const float4*)(Wat + t * 128);
                float a = 0.f;
                for (int k4 = 0; k4 < 32; k4++) {
                    float4 r = r4[k4]; float4 wv = w4[k4];
                    a += r.x * wv.x + r.y * wv.y + r.z * wv.z + r.w * wv.w;
                }
                g_Wpk2[(bid - 129) * 128 + t] = a;
            }
        }
    } else {
        __shared__ __align__(16) float pA[128], pB[128];
        __shared__ float red2[256], red3[256];
        const int j = t & 127, kh = t >> 7;
        const int b0 = (bid - 257) * 2;
        float wf[64], wq[64];
#pragma unroll
        for (int k = 0; k < 64; k++) {
            wf[k] = Wfc1[(kh * 64 + k) * 128 + j];
            wq[k] = Ww  [(kh * 64 + k) * 128 + j];
        }
        if (t < 128) { pA[t] = pool[b0 * 128 + t]; pB[t] = pool[(b0 + 1) * 128 + t]; }
        __syncthreads();
        for (int s = 0; s < Tq; s++) {
            const float4* pa4 = (const float4*)pA; const float4* pb4 = (const float4*)pB;
            float a0 = 0.f, a1 = 0.f;
#pragma unroll
            for (int k4 = 0; k4 < 16; k4++) {
                float4 xa = pa4[kh*16+k4], xb = pb4[kh*16+k4];
                a0 += xa.x*wf[4*k4] + xa.y*wf[4*k4+1] + xa.z*wf[4*k4+2] + xa.w*wf[4*k4+3];
                a1 += xb.x*wf[4*k4] + xb.y*wf[4*k4+1] + xb.z*wf[4*k4+2] + xb.w*wf[4*k4+3];
            }
            red2[t] = a0; red3[t] = a1;
            __syncthreads();
            if (t < 128) { pA[t] = red2[t] + red2[t+128]; pB[t] = red3[t] + red3[t+128]; }
            __syncthreads();
            a0 = 0.f; a1 = 0.f;
#pragma unroll
            for (int k4 = 0; k4 < 16; k4++) {
                float4 xa = pa4[kh*16+k4], xb = pb4[kh*16+k4];
                a0 += xa.x*wq[4*k4] + xa.y*wq[4*k4+1] + xa.z*wq[4*k4+2] + xa.w*wq[4*k4+3];
                a1 += xb.x*wq[4*k4] + xb.y*wq[4*k4+1] + xb.z*wq[4*k4+2] + xb.w*wq[4*k4+3];
            }
            red2[t] = a0; red3[t] = a1;
            __syncthreads();
            if (t < 128) {
                g_poolW[((size_t)b0*Tq + s)*128 + t]     = red2[t] + red2[t+128];
                g_poolW[((size_t)(b0+1)*Tq + s)*128 + t] = red3[t] + red3[t+128];
            }
            __syncthreads();
        }
    }
}

// ---------------------------------------------------------------------------
// prologue matmul: 13-row chunk of one output column; E from global (bcast)
// ---------------------------------------------------------------------------
__device__ __forceinline__ void mm13(const float4* __restrict__ E4,
                                     const float* __restrict__ Wj,
                                     int n0, int cn, float* acc) {
#pragma unroll
    for (int r = 0; r < 13; r++) acc[r] = 0.f;
#pragma unroll 2
    for (int d4 = 0; d4 < 32; d4++) {
        float w0 = Wj[(4*d4+0)*128], w1 = Wj[(4*d4+1)*128];
        float w2 = Wj[(4*d4+2)*128], w3 = Wj[(4*d4+3)*128];
#pragma unroll
        for (int r = 0; r < 13; r++) if (r < cn) {
            float4 e = E4[(n0 + r) * 32 + d4];
            acc[r] = fmaf(e.x, w0, fmaf(e.y, w1, fmaf(e.z, w2, fmaf(e.w, w3, acc[r]))));
        }
    }
}

// ---------------------------------------------------------------------------
// precomp2: per-batch V^T, Kp2^T, G to global (full parallelism, no smem)
// ---------------------------------------------------------------------------
__global__ __launch_bounds__(256)
void precomp2k(const float* __restrict__ enc, const float* __restrict__ Wv) {
    const int t = threadIdx.x, b = blockIdx.x;
    const int j = t & 127;
    const float4* E4 = (const float4*)(enc + (size_t)b * Nq * 128);
    const int nbase = (t >> 7) ? 51 : 0;
    const int ncnt  = (t >> 7) ? 50 : 51;
    float acc[13];

    float* v2 = g_V2 + ((size_t)b * 128 + j) * 104;
    for (int c0 = 0; c0 < ncnt; c0 += 13) {
        int cn = ncnt - c0; if (cn > 13) cn = 13;
        mm13(E4, Wv + j, nbase + c0, cn, acc);
        for (int r = 0; r < cn; r++) v2[nbase + c0 + r] = acc[r];
    }
    v2[101] = 0.f; v2[102] = 0.f; v2[103] = 0.f;

    float* k2 = g_K2 + ((size_t)b * 128 + j) * 104;
    for (int c0 = 0; c0 < ncnt; c0 += 13) {
        int cn = ncnt - c0; if (cn > 13) cn = 13;
        mm13(E4, g_Wpk2 + j, nbase + c0, cn, acc);
        for (int r = 0; r < cn; r++) k2[nbase + c0 + r] = acc[r];
    }
    k2[101] = 0.f; k2[102] = 0.f; k2[103] = 0.f;

    float* gout = g_G + (size_t)b * Nq * 128;
    for (int c0 = 0; c0 < ncnt; c0 += 13) {
        int cn = ncnt - c0; if (cn > 13) cn = 13;
        mm13(E4, g_Wfw + j, nbase + c0, cn, acc);
        for (int r = 0; r < cn; r++) gout[(size_t)(nbase + c0 + r) * 128 + j] = acc[r];
    }
}

// ---------------------------------------------------------------------------
// Main decoder: 1 block / batch row, 256 threads, 56KB smem + 64 regs
// => 4 CTAs/SM => single wave.
// ---------------------------------------------------------------------------
__global__ __launch_bounds__(256, 4)
void decoder_main(const float* __restrict__ enc, const float* __restrict__ capc,
                  const float* __restrict__ demand, const float* __restrict__ Wk,
                  float* __restrict__ out) {
    extern __shared__ __align__(16) float sm[];
    float* KT     = sm;           // 128*101 packed-interleaved K^T
    float* comp   = sm + 12928;   // 8*108
    float* vA     = sm + 13792;   // 128
    float* logits = sm + 13920;   // 104
    float* lsep   = sm + 14024;   // 16
    // total 14040 floats = 56160 B

    const int t = threadIdx.x, b = blockIdx.x;
    const int j = t & 127;
    const int w = t >> 5, lane = t & 31;
    const unsigned FULL = 0xffffffffu;

    const float4* E4 = (const float4*)(enc + (size_t)b * Nq * 128);
    const int nbase = (t >> 7) ? 51 : 0;
    const int ncnt  = (t >> 7) ? 50 : 51;
    const int oq = w * 16 + (lane & 15);
    const int ng = lane >> 4;
    float acc[13];

    // ---- prologue: K^T packed-interleaved into smem -----------------------
    // row d (=j): sub-arrays by k=n&3 at offsets {0,26,51,76}, index n>>2
    for (int c0 = 0; c0 < ncnt; c0 += 13) {
        int cn = ncnt - c0; if (cn > 13) cn = 13;
        mm13(E4, Wk + j, nbase + c0, cn, acc);
        for (int r = 0; r < cn; r++) {
            int n = nbase + c0 + r;
            int k = n & 3, n4 = n >> 2;
            int pos = k ? (26 + (k - 1) * 25 + n4) : n4;
            KT[j * 101 + pos] = acc[r];
        }
    }

    // ---- state init -------------------------------------------------------
    const float cap0 = capc[0];
    float dyn = capc[b];
    float dem4[4];
    unsigned m1b = 0;
#pragma unroll
    for (int k = 0; k < 4; k++) {
        int n = lane + 32 * k;
        dem4[k] = (n < Nq) ? demand[b * Nq + n] : 1e30f;
        if (n == 0 || n >= Nq) m1b |= (1u << k);
    }
    unsigned mw[4];
    {
        unsigned allm = 0xffffffffu;
#pragma unroll
        for (int k = 0; k < 4; k++) {
            int mk = ((m1b >> k) & 1) || (dem4[k] > dyn);
            mw[k] = __ballot_sync(FULL, mk);
            allm &= mw[k];
        }
        if (allm == 0xffffffffu) mw[0] &= ~1u;
    }
    int bi = 0, cnt = 0, par = 0, pgPrev = 1;
    float logp = 0.f, bvP = 0.f;

    const float*  gG  = g_G  + (size_t)b * Nq * 128;
    const float*  gPW = g_poolW + (size_t)b * Tq * 128;
    const float4* gV  = (const float4*)(g_V2 + ((size_t)b * 128 + oq) * 104) + ng * 13;
    const float4* gK2 = (const float4*)(g_K2 + ((size_t)b * 128 + w * 16) * 104);
    const float4* comp4 = (const float4*)comp;

    const float wdyn = g_Wfw[128 * 128 + oq];
    float pw = gPW[oq];
    float qv = gG[oq];
    __syncthreads();     // KT ready

    // =========================== step loop =================================
    for (int step = 0; step < Tq; step++) {
        // ---- fold previous step's log-prob (t==0, off-path) ---------------
        if (t == 0 && step > 0 && pgPrev) {
            int pp = (par ^ 1) * 8;
            float ss = lsep[pp] + lsep[pp+1] + lsep[pp+2] + lsep[pp+3]
                     + lsep[pp+4] + lsep[pp+5] + lsep[pp+6] + lsep[pp+7];
            logp += bvP - logf(ss);
        }
        // ---- Q slice ------------------------------------------------------
        if (lane < 16) {
            vA[oq] = (qv + dyn * wdyn + pw) * 0.25f;
            int sn = step + 1; if (sn >= Tq) sn = Tq - 1;
            pw = gPW[(size_t)sn * 128 + oq];
        }
        __syncwarp();

        // ---- compat (scalar interleaved, conflict-free) -------------------
        // + masked softmax WITH max-subtraction (pool term grows ~2^step,
        //   so compat magnitudes overflow expf without the shift)
        {
            float a0 = 0.f, a1 = 0.f, a2 = 0.f, a3 = 0.f;
#pragma unroll
            for (int dd = 0; dd < 16; dd++) {
                float q = vA[w * 16 + dd];
                const float* kr = KT + (w * 16 + dd) * 101;
                a0 = fmaf(q, kr[lane],      a0);
                a1 = fmaf(q, kr[26 + lane], a1);
                a2 = fmaf(q, kr[51 + lane], a2);
                a3 = fmaf(q, kr[76 + lane], a3);
            }
            unsigned nib = (mw[lane >> 3] >> ((lane & 7) * 4)) & 0xFu;
            if (lane >= 26) nib = 0xFu;
            float v0 = (nib & 1u) ? -INFINITY : a0;
            float v1 = (nib & 2u) ? -INFINITY : a1;
            float v2 = (nib & 4u) ? -INFINITY : a2;
            float v3 = (nib & 8u) ? -INFINITY : a3;
            float mx = fmaxf(fmaxf(v0, v1), fmaxf(v2, v3));
#pragma unroll
            for (int o = 16; o; o >>= 1) mx = fmaxf(mx, __shfl_xor_sync(FULL, mx, o));
            float e0 = (v0 == -INFINITY) ? 0.f : expf(v0 - mx);
            float e1 = (v1 == -INFINITY) ? 0.f : expf(v1 - mx);
            float e2 = (v2 == -INFINITY) ? 0.f : expf(v2 - mx);
            float e3 = (v3 == -INFINITY) ? 0.f : expf(v3 - mx);
            float s = (e0 + e1) + (e2 + e3);
#pragma unroll
            for (int o = 16; o; o >>= 1) s += __shfl_xor_sync(FULL, s, o);
            float inv = 1.f / s;
            if (lane < 26)
                ((float4*)comp)[w * 27 + lane] = make_float4(e0*inv, e1*inv, e2*inv, e3*inv);
        }
        __syncwarp();

        // ---- glimpse: V streamed from L2 (step-invariant addresses) -------
        {
            const float4* cw = comp4 + w * 27 + ng * 13;
            float g0 = 0.f, g1 = 0.f, g2 = 0.f, g3 = 0.f;
#pragma unroll
            for (int c = 0; c < 13; c++) {
                float4 vv = gV[c]; float4 sc = cw[c];
                g0 = fmaf(sc.x, vv.x, g0); g1 = fmaf(sc.y, vv.y, g1);
                g2 = fmaf(sc.z, vv.z, g2); g3 = fmaf(sc.w, vv.w, g3);
            }
            float g = (g0 + g1) + (g2 + g3);
            g += __shfl_xor_sync(FULL, g, 16);
            if (lane < 16) vA[oq] = g;
        }
        __syncwarp();

        // ---- logits partial: Kp2 streamed from L2 -------------------------
        if (lane < 26) {
            float4 a4 = make_float4(0.f, 0.f, 0.f, 0.f);
#pragma unroll
            for (int r = 0; r < 16; r++) {
                float q = vA[w * 16 + r];
                float4 kk = gK2[r * 26 + lane];
                a4.x = fmaf(q, kk.x, a4.x); a4.y = fmaf(q, kk.y, a4.y);
                a4.z = fmaf(q, kk.z, a4.z); a4.w = fmaf(q, kk.w, a4.w);
            }
            ((float4*)comp)[w * 27 + lane] = a4;
        }
        __syncthreads();                                              // bar C

        // ---- logits reduce + tanh + lse partial ---------------------------
        float myLog = -INFINITY;
        if (lane < 13) {
            const int n = 13 * w + lane;
            float sA = comp[n]       + comp[108 + n];
            float sB = comp[216 + n] + comp[324 + n];
            sA += comp[432 + n] + comp[540 + n];
            sB += comp[648 + n] + comp[756 + n];
            float c2 = (sA + sB) * 0.08838834764831845f;
            int msk = (mw[n >> 5] >> (n & 31)) & 1;
            myLog = msk ? -INFINITY : 10.f * tanhf(c2);
            logits[n] = myLog;
        }
        {
            float e = (lane < 13) ? expf(myLog) : 0.f;   // logits bounded ±10
#pragma unroll
            for (int o = 16; o; o >>= 1) e += __shfl_xor_sync(FULL, e, o);
            if (lane == 0) lsep[par * 8 + w] = e;
        }
        __syncthreads();                                              // bar D

        // ---- argmax (redundant in every warp) -----------------------------
        float va0 = logits[lane];
        float va1 = logits[lane + 32];
        float va2 = logits[lane + 64];
        float va3 = (lane + 96 < NP) ? logits[lane + 96] : -INFINITY;
        float bvl = fmaxf(fmaxf(va0, va1), fmaxf(va2, va3));
#pragma unroll
        for (int o = 16; o; o >>= 1) bvl = fmaxf(bvl, __shfl_xor_sync(FULL, bvl, o));
        unsigned cand = 0xFFFFu;
        if (va0 == bvl) cand = lane;
        if (va1 == bvl && (unsigned)(lane + 32) < cand) cand = lane + 32;
        if (va2 == bvl && (unsigned)(lane + 64) < cand) cand = lane + 64;
        if (va3 == bvl && (unsigned)(lane + 96) < cand) cand = lane + 96;
        bi = (int)__reduce_min_sync(FULL, cand);
        pgPrev = (cnt < Nq - 1);   // gate for THIS step's logp (pre-update cnt)
        bvP = bvl;

        if (lane < 16) qv = gG[(size_t)bi * 128 + oq];   // early L2 prefetch
        if (t == 0) out[b * Tq + step] = (float)bi;

        // ---- state update (warp-private registers) ------------------------
        {
            const int ks = bi >> 5, ls = bi & 31;
            float dv = __shfl_sync(FULL, dem4[ks], ls);
            unsigned m1o = __shfl_sync(FULL, m1b, ls);
            int was = (m1o >> ks) & 1;
            if (bi > 0 && !was) cnt++;
            if (bi > 0 && lane == ls) m1b |= (1u << ks);
            if (lane == 0) m1b = (m1b & ~1u) | (bi == 0 ? 1u : 0u);
            dyn = (bi == 0) ? cap0 : (dyn - dv);
            unsigned allm = 0xffffffffu;
#pragma unroll
            for (int k = 0; k < 4; k++) {
                int mk = ((m1b >> k) & 1) || (dem4[k] > dyn);
                mw[k] = __ballot_sync(FULL, mk);
                allm &= mw[k];
            }
            if (allm == 0xffffffffu) mw[0] &= ~1u;
        }
        par ^= 1;
    }

    // ---- tail: fold final step's logp -------------------------------------
    if (t == 0) {
        if (pgPrev) {
            int pp = (par ^ 1) * 8;
            float ss = lsep[pp] + lsep[pp+1] + lsep[pp+2] + lsep[pp+3]
                     + lsep[pp+4] + lsep[pp+5] + lsep[pp+6] + lsep[pp+7];
            logp += bvP - logf(ss);
        }
        out[Bq * Tq + b] = logp;
    }
}

// ---------------------------------------------------------------------------
extern "C" void kernel_launch(void* const* d_in, const int* in_sizes, int n_in,
                              void* d_out, int out_size) {
    const float *enc = nullptr, *pool = nullptr, *capc = nullptr, *dem = nullptr, *Wfc = nullptr;
    const float* w16[8] = {nullptr};
    int nw = 0;
    for (int i = 0; i < n_in; i++) {
        int s = in_sizes[i];
        if      (s == Bq * Nq * 128) enc  = (const float*)d_in[i];
        else if (s == Bq * Hq)       pool = (const float*)d_in[i];
        else if (s == Bq)            capc = (const float*)d_in[i];
        else if (s == Bq * Nq)       dem  = (const float*)d_in[i];
        else if (s == (Hq + 1) * Hq) Wfc  = (const float*)d_in[i];
        else if (s == Hq * Hq) { if (nw < 8) w16[nw++] = (const float*)d_in[i]; }
    }
    // dict order among 128x128: W_fc1, W_w, W_k, W_v, W_attnfc, W_pk
    const float* Wfc1 = w16[0];
    const float* Ww   = w16[1];
    const float* Wk   = w16[2];
    const float* Wv   = w16[3];
    const float* Wat  = w16[4];
    const float* Wpk  = w16[5];

    const int smem_main = 14040 * (int)sizeof(float);   // 56160 B
    cudaFuncSetAttribute(decoder_main, cudaFuncAttributeMaxDynamicSharedMemorySize, smem_main);

    precomp1<<<257 + Bq / 2, 256>>>(Wfc, Ww, Wat, Wpk, pool, Wfc1);
    precomp2k<<<Bq, 256>>>(enc, Wv);
    decoder_main<<<Bq, 256, smem_main>>>(enc, capc, dem, Wk, (float*)d_out);
}

// round 13
// speedup vs baseline: 1.9166x; 1.9166x over previous
#include <cuda_runtime.h>
#include <cuda_bf16.h>
#include <math.h>

#define Bq 512
#define Nq 101
#define Hq 128
#define Tq 140
#define NP 104
#define VSTRIDE 132

// __device__ scratch
__device__ float g_Wfw [129 * 128];                 // Wfc @ Ww
__device__ float g_Wpk2[128 * 128];                 // Wpk @ Wat^T   [k][o]
__device__ float g_poolW[(size_t)Bq * Tq * 128];    // pool@Wfc1^(s+1)@Ww  [b][s][:]
__device__ float g_G[(size_t)Bq * Nq * 128];        // enc@Wfw[:128]       [b][n][:]

// monotone float<->u32 order-preserving map (for REDUX-based float max)
__device__ __forceinline__ unsigned f2mono(float f) {
    unsigned u = __float_as_uint(f);
    return (u & 0x80000000u) ? ~u : (u | 0x80000000u);
}
__device__ __forceinline__ float mono2f(unsigned k) {
    return __uint_as_float((k & 0x80000000u) ? (k & 0x7fffffffu) : ~k);
}

// ---------------------------------------------------------------------------
// P0: fold weights
// ---------------------------------------------------------------------------
__global__ void precomp0(const float* __restrict__ Wfc, const float* __restrict__ Ww,
                         const float* __restrict__ Wat, const float* __restrict__ Wpk) {
    __shared__ __align__(16) float row[128];
    const int t = threadIdx.x, bidx = blockIdx.x;
    if (bidx < 129) {
        row[t] = Wfc[bidx * 128 + t];
        __syncthreads();
        const float4* r4 = (const float4*)row;
        float a = 0.f;
        for (int k4 = 0; k4 < 32; k4++) {
            float4 r = r4[k4];
            a += r.x * Ww[(4 * k4 + 0) * 128 + t] + r.y * Ww[(4 * k4 + 1) * 128 + t]
               + r.z * Ww[(4 * k4 + 2) * 128 + t] + r.w * Ww[(4 * k4 + 3) * 128 + t];
        }
        g_Wfw[bidx * 128 + t] = a;
    } else {
        const int d = bidx - 129;
        row[t] = Wpk[d * 128 + t];
        __syncthreads();
        const float4* r4 = (const float4*)row;
        const float4* w4 = (const float4*)(Wat + t * 128);
        float a = 0.f;
        for (int k4 = 0; k4 < 32; k4++) {
            float4 r = r4[k4]; float4 wv = w4[k4];
            a += r.x * wv.x + r.y * wv.y + r.z * wv.z + r.w * wv.w;
        }
        g_Wpk2[d * 128 + t] = a;
    }
}

// ---------------------------------------------------------------------------
// P2: pool chain folded through Ww. 2 batches/block.
// ---------------------------------------------------------------------------
__global__ __launch_bounds__(256)
void precomp2(const float* __restrict__ pool, const float* __restrict__ Wfc1,
              const float* __restrict__ Ww) {
    __shared__ __align__(16) float pA[128], pB[128];
    __shared__ float red2[256], red3[256];
    const int t = threadIdx.x, j = t & 127, kh = t >> 7;
    const int b0 = blockIdx.x * 2;
    float wf[64], wq[64];
#pragma unroll
    for (int k = 0; k < 64; k++) {
        wf[k] = Wfc1[(kh * 64 + k) * 128 + j];
        wq[k] = Ww  [(kh * 64 + k) * 128 + j];
    }
    if (t < 128) { pA[t] = pool[b0 * 128 + t]; pB[t] = pool[(b0 + 1) * 128 + t]; }
    __syncthreads();
    for (int s = 0; s < Tq; s++) {
        const float4* pa4 = (const float4*)pA; const float4* pb4 = (const float4*)pB;
        float a0 = 0.f, a1 = 0.f;
#pragma unroll
        for (int k4 = 0; k4 < 16; k4++) {
            float4 xa = pa4[kh*16+k4], xb = pb4[kh*16+k4];
            a0 += xa.x*wf[4*k4] + xa.y*wf[4*k4+1] + xa.z*wf[4*k4+2] + xa.w*wf[4*k4+3];
            a1 += xb.x*wf[4*k4] + xb.y*wf[4*k4+1] + xb.z*wf[4*k4+2] + xb.w*wf[4*k4+3];
        }
        red2[t] = a0; red3[t] = a1;
        __syncthreads();
        if (t < 128) { pA[t] = red2[t] + red2[t+128]; pB[t] = red3[t] + red3[t+128]; }
        __syncthreads();
        a0 = 0.f; a1 = 0.f;
#pragma unroll
        for (int k4 = 0; k4 < 16; k4++) {
            float4 xa = pa4[kh*16+k4], xb = pb4[kh*16+k4];
            a0 += xa.x*wq[4*k4] + xa.y*wq[4*k4+1] + xa.z*wq[4*k4+2] + xa.w*wq[4*k4+3];
            a1 += xb.x*wq[4*k4] + xb.y*wq[4*k4+1] + xb.z*wq[4*k4+2] + xb.w*wq[4*k4+3];
        }
        red2[t] = a0; red3[t] = a1;
        __syncthreads();
        if (t < 128) {
            g_poolW[((size_t)b0*Tq + s)*128 + t]     = red2[t] + red2[t+128];
            g_poolW[((size_t)(b0+1)*Tq + s)*128 + t] = red3[t] + red3[t+128];
        }
        __syncthreads();
    }
}

// ---------------------------------------------------------------------------
// prologue matmul: 13-row chunk of one output column; E from global (bcast)
// ---------------------------------------------------------------------------
__device__ __forceinline__ void mm13(const float4* __restrict__ E4,
                                     const float* __restrict__ Wj,
                                     int n0, int cn, float* acc) {
#pragma unroll
    for (int r = 0; r < 13; r++) acc[r] = 0.f;
#pragma unroll 2
    for (int d4 = 0; d4 < 32; d4++) {
        float w0 = Wj[(4*d4+0)*128], w1 = Wj[(4*d4+1)*128];
        float w2 = Wj[(4*d4+2)*128], w3 = Wj[(4*d4+3)*128];
#pragma unroll
        for (int r = 0; r < 13; r++) if (r < cn) {
            float4 e = E4[(n0 + r) * 32 + d4];
            acc[r] = fmaf(e.x, w0, fmaf(e.y, w1, fmaf(e.z, w2, fmaf(e.w, w3, acc[r]))));
        }
    }
}

// ---------------------------------------------------------------------------
// Main decoder: 1 block / batch row, 256 threads, 2 CTAs/SM.
// Warp-redundant decision; 2 block barriers per step; state in registers.
// ---------------------------------------------------------------------------
__global__ __launch_bounds__(256, 2)
void decoder_main(const float* __restrict__ enc, const float* __restrict__ capc,
                  const float* __restrict__ demand, const float* __restrict__ Wk,
                  const float* __restrict__ Wv, float* __restrict__ out) {
    extern __shared__ __align__(16) float sm[];
    float* KT   = sm;                 // 128*104  K^T [d][n] (also Kp2 staging)
    float* Vp   = sm + 13312;         // 104*132  V [n][o] padded
    float* comp = sm + 13312 + 13728; // 8*108 softmax probs / logit partials
    __shared__ __align__(16) float vA[128];
    __shared__ float logits[NP];
    __shared__ float lsep[2][8];

    const int t = threadIdx.x, b = blockIdx.x;
    const int j = t & 127;
    const int w = t >> 5, lane = t & 31;
    const unsigned FULL = 0xffffffffu;

    const float4* E4 = (const float4*)(enc + (size_t)b * Nq * 128);
    const int nbase = (t >> 7) ? 51 : 0;
    const int ncnt  = (t >> 7) ? 50 : 51;
    float acc[13];

    // ---- Phase Kp2: stage Kp2T[d][n] in KT, pick up to registers ----------
    for (int c0 = 0; c0 < ncnt; c0 += 13) {
        int cn = ncnt - c0; if (cn > 13) cn = 13;
        mm13(E4, g_Wpk2 + j, nbase + c0, cn, acc);
        for (int r = 0; r < cn; r++) KT[j * NP + (nbase + c0 + r)] = acc[r];
    }
    if (t < 128) { KT[t * NP + 101] = 0.f; KT[t * NP + 102] = 0.f; KT[t * NP + 103] = 0.f; }
    __syncthreads();
    float4 kp2r4[16];
    {
        const float4* K4 = (const float4*)KT;
        if (lane < 26) {
#pragma unroll
            for (int r = 0; r < 16; r++) kp2r4[r] = K4[(w * 16 + r) * 26 + lane];
        } else {
#pragma unroll
            for (int r = 0; r < 16; r++) kp2r4[r] = make_float4(0.f, 0.f, 0.f, 0.f);
        }
    }
    __syncthreads();

    // ---- Phase V: V[n][o] direct into padded Vp ---------------------------
    for (int c0 = 0; c0 < ncnt; c0 += 13) {
        int cn = ncnt - c0; if (cn > 13) cn = 13;
        mm13(E4, Wv + j, nbase + c0, cn, acc);
        for (int r = 0; r < cn; r++) Vp[(nbase + c0 + r) * VSTRIDE + j] = acc[r];
    }
    if (t < 128) {
        Vp[101 * VSTRIDE + t] = 0.f; Vp[102 * VSTRIDE + t] = 0.f; Vp[103 * VSTRIDE + t] = 0.f;
    }

    // ---- Phase K: K^T[d][n] final resident in KT --------------------------
    for (int c0 = 0; c0 < ncnt; c0 += 13) {
        int cn = ncnt - c0; if (cn > 13) cn = 13;
        mm13(E4, Wk + j, nbase + c0, cn, acc);
        for (int r = 0; r < cn; r++) KT[j * NP + (nbase + c0 + r)] = acc[r];
    }
    if (t < 128) { KT[t * NP + 101] = 0.f; KT[t * NP + 102] = 0.f; KT[t * NP + 103] = 0.f; }

    // ---- Phase G: g_G[b][n][:] = E @ Wfw[:128] ----------------------------
    {
        float* gout = g_G + (size_t)b * Nq * 128;
        for (int c0 = 0; c0 < ncnt; c0 += 13) {
            int cn = ncnt - c0; if (cn > 13) cn = 13;
            mm13(E4, g_Wfw + j, nbase + c0, cn, acc);
            for (int r = 0; r < cn; r++) gout[(size_t)(nbase + c0 + r) * 128 + j] = acc[r];
        }
    }
    __syncthreads();   // all tiles + g_G ready

    // ---- warp-private register state --------------------------------------
    const float cap0 = capc[0];
    float dyn = capc[b];
    float dem4[4];
    unsigned m1b = 0;          // bit k: mask1 for n = lane + 32k
#pragma unroll
    for (int k = 0; k < 4; k++) {
        int n = lane + 32 * k;
        dem4[k] = (n < Nq) ? demand[b * Nq + n] : 1e30f;
        if (n == 0 || n >= Nq) m1b |= (1u << k);
    }
    unsigned mw[4];            // warp-uniform mask words (bit n%32 of word n/32)
    {
        unsigned allm = 0xffffffffu;
#pragma unroll
        for (int k = 0; k < 4; k++) {
            int mk = ((m1b >> k) & 1) || (dem4[k] > dyn);
            mw[k] = __ballot_sync(FULL, mk);
            allm &= mw[k];
        }
        if (allm == 0xffffffffu) mw[0] &= ~1u;
    }
    int bi = 0, cnt = 0, pg = 1, par = 0;
    float logp = 0.f;

    const float4* KT4 = (const float4*)KT;
    const float4* vA4 = (const float4*)vA;
    float4* comp4 = (float4*)comp;
    const float* gG  = g_G + (size_t)b * Nq * 128;
    const float* gPW = g_poolW + (size_t)b * Tq * 128;

    const int oq = w * 16 + (lane & 15);
    const int ng = lane >> 4;
    const float wdyn = g_Wfw[128 * 128 + oq];
    float pw = gPW[oq];
    float qv = gG[oq];         // G row for initial index 0

    // =========================== step loop =================================
    for (int step = 0; step < Tq; step++) {
        // ---- Q slice (lanes 0-15 per warp); qv preloaded ------------------
        if (lane < 16) {
            vA[oq] = (qv + dyn * wdyn + pw) * 0.25f;
            int sn = step + 1; if (sn >= Tq) sn = Tq - 1;
            pw = gPW[(size_t)sn * 128 + oq];
        }
        __syncwarp();

        // ---- compat + masked softmax (in-warp, head w) --------------------
        {
            float4 a4 = make_float4(0.f, 0.f, 0.f, 0.f);
            if (lane < 26) {
#pragma unroll
                for (int d4 = 0; d4 < 4; d4++) {
                    float4 q = vA4[w * 4 + d4];
                    float4 k0 = KT4[(w * 16 + d4 * 4 + 0) * 26 + lane];
                    float4 k1 = KT4[(w * 16 + d4 * 4 + 1) * 26 + lane];
                    float4 k2 = KT4[(w * 16 + d4 * 4 + 2) * 26 + lane];
                    float4 k3 = KT4[(w * 16 + d4 * 4 + 3) * 26 + lane];
                    a4.x += q.x*k0.x + q.y*k1.x + q.z*k2.x + q.w*k3.x;
                    a4.y += q.x*k0.y + q.y*k1.y + q.z*k2.y + q.w*k3.y;
                    a4.z += q.x*k0.z + q.y*k1.z + q.z*k2.z + q.w*k3.z;
                    a4.w += q.x*k0.w + q.y*k1.w + q.z*k2.w + q.w*k3.w;
                }
            }
            unsigned nib = (mw[lane >> 3] >> ((lane & 7) * 4)) & 0xFu;
            if (lane >= 26) nib = 0xFu;
            float v0 = (nib & 1u) ? -INFINITY : a4.x;
            float v1 = (nib & 2u) ? -INFINITY : a4.y;
            float v2 = (nib & 4u) ? -INFINITY : a4.z;
            float v3 = (nib & 8u) ? -INFINITY : a4.w;
            // max via REDUX on monotone-mapped value (replaces 5-shfl tree)
            float mx = mono2f(__reduce_max_sync(FULL,
                        f2mono(fmaxf(fmaxf(v0, v1), fmaxf(v2, v3)))));
            // mx is finite (>=1 open node always); expf(-inf - mx) = 0
            float e0 = __expf(v0 - mx);
            float e1 = __expf(v1 - mx);
            float e2 = __expf(v2 - mx);
            float e3 = __expf(v3 - mx);
            float s = (e0 + e1) + (e2 + e3);
#pragma unroll
            for (int o = 16; o; o >>= 1) s += __shfl_xor_sync(FULL, s, o);
            float inv = 1.f / s;
            if (lane < 26)
                comp4[w * 27 + lane] = make_float4(e0 * inv, e1 * inv, e2 * inv, e3 * inv);
        }
        __syncwarp();

        // ---- glimpse (in-warp): dims [16w,16w+16), V from padded smem -----
        {
            const float* vp = Vp + ng * 52 * VSTRIDE + oq;
            const float4* cw = comp4 + w * 27 + ng * 13;
            float g = 0.f;
#pragma unroll
            for (int c = 0; c < 13; c++) {
                float4 sc = cw[c];
                g += sc.x * vp[(4*c+0)*VSTRIDE] + sc.y * vp[(4*c+1)*VSTRIDE]
                   + sc.z * vp[(4*c+2)*VSTRIDE] + sc.w * vp[(4*c+3)*VSTRIDE];
            }
            g += __shfl_xor_sync(FULL, g, 16);
            if (lane < 16) vA[oq] = g;
        }
        __syncwarp();

        // ---- logits partial (own vA slice, Kp2 in regs) -> comp row w -----
        if (lane < 26) {
            float4 a4 = make_float4(0.f, 0.f, 0.f, 0.f);
#pragma unroll
            for (int d4 = 0; d4 < 4; d4++) {
                float4 q = vA4[w * 4 + d4];
                float4 k0 = kp2r4[d4 * 4 + 0];
                float4 k1 = kp2r4[d4 * 4 + 1];
                float4 k2 = kp2r4[d4 * 4 + 2];
                float4 k3 = kp2r4[d4 * 4 + 3];
                a4.x += q.x*k0.x + q.y*k1.x + q.z*k2.x + q.w*k3.x;
                a4.y += q.x*k0.y + q.y*k1.y + q.z*k2.y + q.w*k3.y;
                a4.z += q.x*k0.z + q.y*k1.z + q.z*k2.z + q.w*k3.z;
                a4.w += q.x*k0.w + q.y*k1.w + q.z*k2.w + q.w*k3.w;
            }
            comp4[w * 27 + lane] = a4;
        }
        __syncthreads();                                              // bar C

        // ---- warp w: logits slice n in [13w, 13w+13) ----------------------
        if (lane < 13) {
            const int n = 13 * w + lane;
            float s = comp[n];
#pragma unroll
            for (int k = 1; k < 8; k++) s += comp[k * 108 + n];
            float c2 = s * 0.08838834764831845f;
            int msk = (mw[n >> 5] >> (n & 31)) & 1;
            logits[n] = msk ? -INFINITY : 10.f * tanhf(c2);
        }
        __syncthreads();                                              // bar D

        // ---- argmax: local 4-slot max + REDUX value + min-index -----------
        float va0 = logits[lane];
        float va1 = logits[lane + 32];
        float va2 = logits[lane + 64];
        float va3 = (lane + 96 < NP) ? logits[lane + 96] : -INFINITY;
        float bl = va0; int bn = lane;                // strict > keeps first idx
        if (va1 > bl) { bl = va1; bn = lane + 32; }
        if (va2 > bl) { bl = va2; bn = lane + 64; }
        if (va3 > bl) { bl = va3; bn = lane + 96; }
        float bv = mono2f(__reduce_max_sync(FULL, f2mono(bl)));
        unsigned cand = (bl == bv) ? (unsigned)bn : 0xFFFFu;
        bi = (int)__reduce_min_sync(FULL, cand);

        // ---- early G load for next step (hides L2 latency) ----------------
        if (lane < 16) qv = gG[(size_t)bi * 128 + oq];

        // ---- warp0: fold previous step's lse partials ---------------------
        if (w == 0 && lane == 0 && step > 0 && pg) {
            float ss = lsep[par ^ 1][0] + lsep[par ^ 1][1] + lsep[par ^ 1][2]
                     + lsep[par ^ 1][3] + lsep[par ^ 1][4] + lsep[par ^ 1][5]
                     + lsep[par ^ 1][6] + lsep[par ^ 1][7];
            logp -= logf(ss);
        }
        if (w == 0 && lane == 0) out[b * Tq + step] = (float)bi;

        // ---- state update (warp-private registers) ------------------------
        {
            const int ks = bi >> 5, ls = bi & 31;
            float dv = __shfl_sync(FULL, dem4[ks], ls);
            unsigned m1o = __shfl_sync(FULL, m1b, ls);
            int was = (m1o >> ks) & 1;
            pg = (cnt < Nq - 1);
            if (bi > 0 && !was) cnt++;
            if (bi > 0 && lane == ls) m1b |= (1u << ks);
            if (lane == 0) m1b = (m1b & ~1u) | (bi == 0 ? 1u : 0u);
            dyn = (bi == 0) ? cap0 : (dyn - dv);
            unsigned allm = 0xffffffffu;
#pragma unroll
            for (int k = 0; k < 4; k++) {
                int mk = ((m1b >> k) & 1) || (dem4[k] > dyn);
                mw[k] = __ballot_sync(FULL, mk);
                allm &= mw[k];
            }
            if (allm == 0xffffffffu) mw[0] &= ~1u;
        }

        // ---- lse partial for this step (slice [13w,13w+13)) ---------------
        {
            float e = 0.f;
            if (lane < 13) e = expf(logits[13 * w + lane] - bv);  // -inf -> 0
#pragma unroll
            for (int o = 8; o; o >>= 1) e += __shfl_xor_sync(FULL, e, o);
            if (lane == 0) lsep[par][w] = e;
        }
        par ^= 1;
    }

    __syncthreads();
    if (w == 0 && lane == 0) {
        if (pg) {
            float ss = lsep[par ^ 1][0] + lsep[par ^ 1][1] + lsep[par ^ 1][2]
                     + lsep[par ^ 1][3] + lsep[par ^ 1][4] + lsep[par ^ 1][5]
                     + lsep[par ^ 1][6] + lsep[par ^ 1][7];
            logp -= logf(ss);
        }
        out[Bq * Tq + b] = logp;
    }
}

// ---------------------------------------------------------------------------
extern "C" void kernel_launch(void* const* d_in, const int* in_sizes, int n_in,
                              void* d_out, int out_size) {
    const float *enc = nullptr, *pool = nullptr, *capc = nullptr, *dem = nullptr, *Wfc = nullptr;
    const float* w16[8] = {nullptr};
    int nw = 0;
    for (int i = 0; i < n_in; i++) {
        int s = in_sizes[i];
        if      (s == Bq * Nq * 128) enc  = (const float*)d_in[i];
        else if (s == Bq * Hq)       pool = (const float*)d_in[i];
        else if (s == Bq)            capc = (const float*)d_in[i];
        else if (s == Bq * Nq)       dem  = (const float*)d_in[i];
        else if (s == (Hq + 1) * Hq) Wfc  = (const float*)d_in[i];
        else if (s == Hq * Hq) { if (nw < 8) w16[nw++] = (const float*)d_in[i]; }
    }
    // dict order among 128x128: W_fc1, W_w, W_k, W_v, W_attnfc, W_pk
    const float* Wfc1 = w16[0];
    const float* Ww   = w16[1];
    const float* Wk   = w16[2];
    const float* Wv   = w16[3];
    const float* Wat  = w16[4];
    const float* Wpk  = w16[5];

    const int smem_main = (13312 + 13728 + 864) * (int)sizeof(float);  // 111616 B
    cudaFuncSetAttribute(decoder_main, cudaFuncAttributeMaxDynamicSharedMemorySize, smem_main);

    precomp0<<<257, 128>>>(Wfc, Ww, Wat, Wpk);
    precomp2<<<Bq / 2, 256>>>(pool, Wfc1, Ww);
    decoder_main<<<Bq, 256, smem_main>>>(enc, capc, dem, Wk, Wv, (float*)d_out);
}

// round 16
// speedup vs baseline: 2.0408x; 1.0648x over previous
#include <cuda_runtime.h>
#include <cuda_bf16.h>
#include <math.h>

#define Bq 512
#define Nq 101
#define Hq 128
#define Tq 140
#define NP 104
#define VSTRIDE 132

// __device__ scratch
__device__ float g_Wfw [129 * 128];                 // Wfc @ Ww
__device__ float g_Wpk2[128 * 128];                 // Wpk @ Wat^T   [k][o]
__device__ float g_pool [(size_t)Bq * Tq * 128];    // pool@Wfc1^(s+1)        [b][s][:]
__device__ float g_poolW[(size_t)Bq * Tq * 128];    // pool@Wfc1^(s+1)@Ww     [b][s][:]
__device__ float g_G[(size_t)Bq * Nq * 128];        // enc@Wfw[:128]          [b][n][:]

// monotone float<->u32 order-preserving map (for REDUX-based float max)
__device__ __forceinline__ unsigned f2mono(float f) {
    unsigned u = __float_as_uint(f);
    return (u & 0x80000000u) ? ~u : (u | 0x80000000u);
}
__device__ __forceinline__ float mono2f(unsigned k) {
    return __uint_as_float((k & 0x80000000u) ? (k & 0x7fffffffu) : ~k);
}

// ---------------------------------------------------------------------------
// P0: fold weights
// ---------------------------------------------------------------------------
__global__ void precomp0(const float* __restrict__ Wfc, const float* __restrict__ Ww,
                         const float* __restrict__ Wat, const float* __restrict__ Wpk) {
    __shared__ __align__(16) float row[128];
    const int t = threadIdx.x, bidx = blockIdx.x;
    if (bidx < 129) {
        row[t] = Wfc[bidx * 128 + t];
        __syncthreads();
        const float4* r4 = (const float4*)row;
        float a = 0.f;
        for (int k4 = 0; k4 < 32; k4++) {
            float4 r = r4[k4];
            a += r.x * Ww[(4 * k4 + 0) * 128 + t] + r.y * Ww[(4 * k4 + 1) * 128 + t]
               + r.z * Ww[(4 * k4 + 2) * 128 + t] + r.w * Ww[(4 * k4 + 3) * 128 + t];
        }
        g_Wfw[bidx * 128 + t] = a;
    } else {
        const int d = bidx - 129;
        row[t] = Wpk[d * 128 + t];
        __syncthreads();
        const float4* r4 = (const float4*)row;
        const float4* w4 = (const float4*)(Wat + t * 128);
        float a = 0.f;
        for (int k4 = 0; k4 < 32; k4++) {
            float4 r = r4[k4]; float4 wv = w4[k4];
            a += r.x * wv.x + r.y * wv.y + r.z * wv.z + r.w * wv.w;
        }
        g_Wpk2[d * 128 + t] = a;
    }
}

// ---------------------------------------------------------------------------
// P2a: pool chain ONLY (half the serial work of old P2). 2 batches/block.
// ---------------------------------------------------------------------------
__global__ __launch_bounds__(256)
void precomp2a(const float* __restrict__ pool, const float* __restrict__ Wfc1) {
    __shared__ __align__(16) float pA[128], pB[128];
    __shared__ float red2[256], red3[256];
    const int t = threadIdx.x, j = t & 127, kh = t >> 7;
    const int b0 = blockIdx.x * 2;
    float wf[64];
#pragma unroll
    for (int k = 0; k < 64; k++) wf[k] = Wfc1[(kh * 64 + k) * 128 + j];
    if (t < 128) { pA[t] = pool[b0 * 128 + t]; pB[t] = pool[(b0 + 1) * 128 + t]; }
    __syncthreads();
    for (int s = 0; s < Tq; s++) {
        const float4* pa4 = (const float4*)pA; const float4* pb4 = (const float4*)pB;
        float a0 = 0.f, a1 = 0.f;
#pragma unroll
        for (int k4 = 0; k4 < 16; k4++) {
            float4 xa = pa4[kh*16+k4], xb = pb4[kh*16+k4];
            a0 += xa.x*wf[4*k4] + xa.y*wf[4*k4+1] + xa.z*wf[4*k4+2] + xa.w*wf[4*k4+3];
            a1 += xb.x*wf[4*k4] + xb.y*wf[4*k4+1] + xb.z*wf[4*k4+2] + xb.w*wf[4*k4+3];
        }
        red2[t] = a0; red3[t] = a1;
        __syncthreads();
        if (t < 128) {
            float na = red2[t] + red2[t + 128];
            float nb = red3[t] + red3[t + 128];
            pA[t] = na; pB[t] = nb;
            g_pool[((size_t)b0 * Tq + s) * 128 + t]       = na;
            g_pool[((size_t)(b0 + 1) * Tq + s) * 128 + t] = nb;
        }
        __syncthreads();
    }
}

// ---------------------------------------------------------------------------
// P2b: g_poolW = g_pool @ Ww  (parallel GEMM, 16 rows/block for Ww reuse)
// ---------------------------------------------------------------------------
__global__ __launch_bounds__(256)
void precomp2b(const float* __restrict__ Ww) {
    __shared__ __align__(16) float P[16 * 128];
    const int t = threadIdx.x;
    const size_t row0 = (size_t)blockIdx.x * 16;
    for (int i = t; i < 16 * 128; i += 256) P[i] = g_pool[row0 * 128 + i];
    __syncthreads();
    const int j = t & 127, half = t >> 7;
    float acc[8];
#pragma unroll
    for (int r = 0; r < 8; r++) acc[r] = 0.f;
    for (int d = 0; d < 128; d++) {
        float wv = Ww[d * 128 + j];
#pragma unroll
        for (int r = 0; r < 8; r++) acc[r] += P[(half * 8 + r) * 128 + d] * wv;
    }
#pragma unroll
    for (int r = 0; r < 8; r++)
        g_poolW[(row0 + half * 8 + r) * 128 + j] = acc[r];
}

// ---------------------------------------------------------------------------
// prologue matmul: 13-row chunk of one output column; E from global (bcast)
// ---------------------------------------------------------------------------
__device__ __forceinline__ void mm13(const float4* __restrict__ E4,
                                     const float* __restrict__ Wj,
                                     int n0, int cn, float* acc) {
#pragma unroll
    for (int r = 0; r < 13; r++) acc[r] = 0.f;
#pragma unroll 2
    for (int d4 = 0; d4 < 32; d4++) {
        float w0 = Wj[(4*d4+0)*128], w1 = Wj[(4*d4+1)*128];
        float w2 = Wj[(4*d4+2)*128], w3 = Wj[(4*d4+3)*128];
#pragma unroll
        for (int r = 0; r < 13; r++) if (r < cn) {
            float4 e = E4[(n0 + r) * 32 + d4];
            acc[r] = fmaf(e.x, w0, fmaf(e.y, w1, fmaf(e.z, w2, fmaf(e.w, w3, acc[r]))));
        }
    }
}

// ---------------------------------------------------------------------------
// Main decoder: 1 block / batch row, 256 threads, 2 CTAs/SM.
// Warp-redundant decision; 2 block barriers per step; state in registers.
// ---------------------------------------------------------------------------
__global__ __launch_bounds__(256, 2)
void decoder_main(const float* __restrict__ enc, const float* __restrict__ capc,
                  const float* __restrict__ demand, const float* __restrict__ Wk,
                  const float* __restrict__ Wv, float* __restrict__ out) {
    extern __shared__ __align__(16) float sm[];
    float* KT   = sm;                 // 128*104  K^T [d][n] (also Kp2 staging)
    float* Vp   = sm + 13312;         // 104*132  V [n][o] padded
    float* comp = sm + 13312 + 13728; // 8*108 softmax exps / logit partials
    __shared__ __align__(16) float vA[128];
    __shared__ float logits[NP];
    __shared__ float lsep[2][8];

    const int t = threadIdx.x, b = blockIdx.x;
    const int j = t & 127;
    const int w = t >> 5, lane = t & 31;
    const unsigned FULL = 0xffffffffu;

    const float4* E4 = (const float4*)(enc + (size_t)b * Nq * 128);
    const int nbase = (t >> 7) ? 51 : 0;
    const int ncnt  = (t >> 7) ? 50 : 51;
    float acc[13];

    // ---- Phase Kp2: stage Kp2T[d][n] in KT, pick up to registers ----------
    for (int c0 = 0; c0 < ncnt; c0 += 13) {
        int cn = ncnt - c0; if (cn > 13) cn = 13;
        mm13(E4, g_Wpk2 + j, nbase + c0, cn, acc);
        for (int r = 0; r < cn; r++) KT[j * NP + (nbase + c0 + r)] = acc[r];
    }
    if (t < 128) { KT[t * NP + 101] = 0.f; KT[t * NP + 102] = 0.f; KT[t * NP + 103] = 0.f; }
    __syncthreads();
    float4 kp2r4[16];
    {
        const float4* K4 = (const float4*)KT;
        if (lane < 26) {
#pragma unroll
            for (int r = 0; r < 16; r++) kp2r4[r] = K4[(w * 16 + r) * 26 + lane];
        } else {
#pragma unroll
            for (int r = 0; r < 16; r++) kp2r4[r] = make_float4(0.f, 0.f, 0.f, 0.f);
        }
    }
    __syncthreads();

    // ---- Phase V: V[n][o] direct into padded Vp ---------------------------
    for (int c0 = 0; c0 < ncnt; c0 += 13) {
        int cn = ncnt - c0; if (cn > 13) cn = 13;
        mm13(E4, Wv + j, nbase + c0, cn, acc);
        for (int r = 0; r < cn; r++) Vp[(nbase + c0 + r) * VSTRIDE + j] = acc[r];
    }
    if (t < 128) {
        Vp[101 * VSTRIDE + t] = 0.f; Vp[102 * VSTRIDE + t] = 0.f; Vp[103 * VSTRIDE + t] = 0.f;
    }

    // ---- Phase K: K^T[d][n] final resident in KT --------------------------
    for (int c0 = 0; c0 < ncnt; c0 += 13) {
        int cn = ncnt - c0; if (cn > 13) cn = 13;
        mm13(E4, Wk + j, nbase + c0, cn, acc);
        for (int r = 0; r < cn; r++) KT[j * NP + (nbase + c0 + r)] = acc[r];
    }
    if (t < 128) { KT[t * NP + 101] = 0.f; KT[t * NP + 102] = 0.f; KT[t * NP + 103] = 0.f; }

    // ---- Phase G: g_G[b][n][:] = E @ Wfw[:128] ----------------------------
    {
        float* gout = g_G + (size_t)b * Nq * 128;
        for (int c0 = 0; c0 < ncnt; c0 += 13) {
            int cn = ncnt - c0; if (cn > 13) cn = 13;
            mm13(E4, g_Wfw + j, nbase + c0, cn, acc);
            for (int r = 0; r < cn; r++) gout[(size_t)(nbase + c0 + r) * 128 + j] = acc[r];
        }
    }
    __syncthreads();   // all tiles + g_G ready

    // ---- warp-private register state --------------------------------------
    const float cap0 = capc[0];
    float dyn = capc[b];
    float dem4[4];
    unsigned m1b = 0;          // bit k: mask1 for n = lane + 32k
#pragma unroll
    for (int k = 0; k < 4; k++) {
        int n = lane + 32 * k;
        dem4[k] = (n < Nq) ? demand[b * Nq + n] : 1e30f;
        if (n == 0 || n >= Nq) m1b |= (1u << k);
    }
    unsigned mw[4];            // warp-uniform mask words (bit n%32 of word n/32)
    {
        unsigned allm = 0xffffffffu;
#pragma unroll
        for (int k = 0; k < 4; k++) {
            int mk = ((m1b >> k) & 1) || (dem4[k] > dyn);
            mw[k] = __ballot_sync(FULL, mk);
            allm &= mw[k];
        }
        if (allm == 0xffffffffu) mw[0] &= ~1u;
    }
    int bi = 0, cnt = 0, pg = 1, par = 0;
    float logp = 0.f;

    const float4* KT4 = (const float4*)KT;
    const float4* vA4 = (const float4*)vA;
    float4* comp4 = (float4*)comp;
    const float* gG  = g_G + (size_t)b * Nq * 128;
    const float* gPW = g_poolW + (size_t)b * Tq * 128;

    const int oq = w * 16 + (lane & 15);
    const int ng = lane >> 4;
    const float wdyn = g_Wfw[128 * 128 + oq];
    float pw = gPW[oq];
    float qv = gG[oq];         // G row for initial index 0

    // =========================== step loop =================================
    for (int step = 0; step < Tq; step++) {
        // ---- Q slice (lanes 0-15 per warp); qv preloaded ------------------
        if (lane < 16) {
            vA[oq] = (qv + dyn * wdyn + pw) * 0.25f;
            int sn = step + 1; if (sn >= Tq) sn = Tq - 1;
            pw = gPW[(size_t)sn * 128 + oq];
        }
        __syncwarp();

        // ---- compat + masked softmax (in-warp, head w) --------------------
        // comp gets UNNORMALIZED exps (store before sum tree); 1/s folded
        // into the glimpse output below.
        float ssum;
        {
            float4 a4 = make_float4(0.f, 0.f, 0.f, 0.f);
            if (lane < 26) {
#pragma unroll
                for (int d4 = 0; d4 < 4; d4++) {
                    float4 q = vA4[w * 4 + d4];
                    float4 k0 = KT4[(w * 16 + d4 * 4 + 0) * 26 + lane];
                    float4 k1 = KT4[(w * 16 + d4 * 4 + 1) * 26 + lane];
                    float4 k2 = KT4[(w * 16 + d4 * 4 + 2) * 26 + lane];
                    float4 k3 = KT4[(w * 16 + d4 * 4 + 3) * 26 + lane];
                    a4.x += q.x*k0.x + q.y*k1.x + q.z*k2.x + q.w*k3.x;
                    a4.y += q.x*k0.y + q.y*k1.y + q.z*k2.y + q.w*k3.y;
                    a4.z += q.x*k0.z + q.y*k1.z + q.z*k2.z + q.w*k3.z;
                    a4.w += q.x*k0.w + q.y*k1.w + q.z*k2.w + q.w*k3.w;
                }
            }
            unsigned nib = (mw[lane >> 3] >> ((lane & 7) * 4)) & 0xFu;
            if (lane >= 26) nib = 0xFu;
            float v0 = (nib & 1u) ? -INFINITY : a4.x;
            float v1 = (nib & 2u) ? -INFINITY : a4.y;
            float v2 = (nib & 4u) ? -INFINITY : a4.z;
            float v3 = (nib & 8u) ? -INFINITY : a4.w;
            float mx = mono2f(__reduce_max_sync(FULL,
                        f2mono(fmaxf(fmaxf(v0, v1), fmaxf(v2, v3)))));
            float e0 = __expf(v0 - mx);
            float e1 = __expf(v1 - mx);
            float e2 = __expf(v2 - mx);
            float e3 = __expf(v3 - mx);
            if (lane < 26)
                comp4[w * 27 + lane] = make_float4(e0, e1, e2, e3);
            float s = (e0 + e1) + (e2 + e3);
#pragma unroll
            for (int o = 16; o; o >>= 1) s += __shfl_xor_sync(FULL, s, o);
            ssum = s;
        }
        __syncwarp();

        // ---- glimpse (in-warp): dims [16w,16w+16), V from padded smem -----
        {
            const float* vp = Vp + ng * 52 * VSTRIDE + oq;
            const float4* cw = comp4 + w * 27 + ng * 13;
            float g = 0.f;
#pragma unroll
            for (int c = 0; c < 13; c++) {
                float4 sc = cw[c];
                g += sc.x * vp[(4*c+0)*VSTRIDE] + sc.y * vp[(4*c+1)*VSTRIDE]
                   + sc.z * vp[(4*c+2)*VSTRIDE] + sc.w * vp[(4*c+3)*VSTRIDE];
            }
            g += __shfl_xor_sync(FULL, g, 16);
            if (lane < 16) vA[oq] = __fdividef(g, ssum);   // deferred softmax norm
        }
        __syncwarp();

        // ---- logits partial (own vA slice, Kp2 in regs) -> comp row w -----
        if (lane < 26) {
            float4 a4 = make_float4(0.f, 0.f, 0.f, 0.f);
#pragma unroll
            for (int d4 = 0; d4 < 4; d4++) {
                float4 q = vA4[w * 4 + d4];
                float4 k0 = kp2r4[d4 * 4 + 0];
                float4 k1 = kp2r4[d4 * 4 + 1];
                float4 k2 = kp2r4[d4 * 4 + 2];
                float4 k3 = kp2r4[d4 * 4 + 3];
                a4.x += q.x*k0.x + q.y*k1.x + q.z*k2.x + q.w*k3.x;
                a4.y += q.x*k0.y + q.y*k1.y + q.z*k2.y + q.w*k3.y;
                a4.z += q.x*k0.z + q.y*k1.z + q.z*k2.z + q.w*k3.z;
                a4.w += q.x*k0.w + q.y*k1.w + q.z*k2.w + q.w*k3.w;
            }
            comp4[w * 27 + lane] = a4;
        }
        __syncthreads();                                              // bar C

        // ---- warp w: logits slice n in [13w, 13w+13) ----------------------
        if (lane < 13) {
            const int n = 13 * w + lane;
            float s = comp[n];
#pragma unroll
            for (int k = 1; k < 8; k++) s += comp[k * 108 + n];
            float c2 = s * 0.08838834764831845f;
            int msk = (mw[n >> 5] >> (n & 31)) & 1;
            logits[n] = msk ? -INFINITY : 10.f * tanhf(c2);
        }
        __syncthreads();                                              // bar D

        // ---- argmax: local 4-slot max + REDUX value + min-index -----------
        float va0 = logits[lane];
        float va1 = logits[lane + 32];
        float va2 = logits[lane + 64];
        float va3 = (lane + 96 < NP) ? logits[lane + 96] : -INFINITY;
        float bl = va0; int bn = lane;                // strict > keeps first idx
        if (va1 > bl) { bl = va1; bn = lane + 32; }
        if (va2 > bl) { bl = va2; bn = lane + 64; }
        if (va3 > bl) { bl = va3; bn = lane + 96; }
        float bv = mono2f(__reduce_max_sync(FULL, f2mono(bl)));
        unsigned cand = (bl == bv) ? (unsigned)bn : 0xFFFFu;
        bi = (int)__reduce_min_sync(FULL, cand);

        // ---- early G load for next step (hides L2 latency) ----------------
        if (lane < 16) qv = gG[(size_t)bi * 128 + oq];

        // ---- warp0: fold previous step's lse partials ---------------------
        if (w == 0 && lane == 0 && step > 0 && pg) {
            float ss = lsep[par ^ 1][0] + lsep[par ^ 1][1] + lsep[par ^ 1][2]
                     + lsep[par ^ 1][3] + lsep[par ^ 1][4] + lsep[par ^ 1][5]
                     + lsep[par ^ 1][6] + lsep[par ^ 1][7];
            logp -= logf(ss);
        }
        if (w == 0 && lane == 0) out[b * Tq + step] = (float)bi;

        // ---- state update (warp-private registers) ------------------------
        {
            const int ks = bi >> 5, ls = bi & 31;
            float dv = __shfl_sync(FULL, dem4[ks], ls);
            unsigned m1o = __shfl_sync(FULL, m1b, ls);
            int was = (m1o >> ks) & 1;
            pg = (cnt < Nq - 1);
            if (bi > 0 && !was) cnt++;
            if (bi > 0 && lane == ls) m1b |= (1u << ks);
            if (lane == 0) m1b = (m1b & ~1u) | (bi == 0 ? 1u : 0u);
            dyn = (bi == 0) ? cap0 : (dyn - dv);
            unsigned allm = 0xffffffffu;
#pragma unroll
            for (int k = 0; k < 4; k++) {
                int mk = ((m1b >> k) & 1) || (dem4[k] > dyn);
                mw[k] = __ballot_sync(FULL, mk);
                allm &= mw[k];
            }
            if (allm == 0xffffffffu) mw[0] &= ~1u;
        }

        // ---- lse partial for this step (slice [13w,13w+13)) ---------------
        {
            float e = 0.f;
            if (lane < 13) e = __expf(logits[13 * w + lane] - bv);  // -inf -> 0
#pragma unroll
            for (int o = 8; o; o >>= 1) e += __shfl_xor_sync(FULL, e, o);
            if (lane == 0) lsep[par][w] = e;
        }
        par ^= 1;
    }

    __syncthreads();
    if (w == 0 && lane == 0) {
        if (pg) {
            float ss = lsep[par ^ 1][0] + lsep[par ^ 1][1] + lsep[par ^ 1][2]
                     + lsep[par ^ 1][3] + lsep[par ^ 1][4] + lsep[par ^ 1][5]
                     + lsep[par ^ 1][6] + lsep[par ^ 1][7];
            logp -= logf(ss);
        }
        out[Bq * Tq + b] = logp;
    }
}

// ---------------------------------------------------------------------------
extern "C" void kernel_launch(void* const* d_in, const int* in_sizes, int n_in,
                              void* d_out, int out_size) {
    const float *enc = nullptr, *pool = nullptr, *capc = nullptr, *dem = nullptr, *Wfc = nullptr;
    const float* w16[8] = {nullptr};
    int nw = 0;
    for (int i = 0; i < n_in; i++) {
        int s = in_sizes[i];
        if      (s == Bq * Nq * 128) enc  = (const float*)d_in[i];
        else if (s == Bq * Hq)       pool = (const float*)d_in[i];
        else if (s == Bq)            capc = (const float*)d_in[i];
        else if (s == Bq * Nq)       dem  = (const float*)d_in[i];
        else if (s == (Hq + 1) * Hq) Wfc  = (const float*)d_in[i];
        else if (s == Hq * Hq) { if (nw < 8) w16[nw++] = (const float*)d_in[i]; }
    }
    // dict order among 128x128: W_fc1, W_w, W_k, W_v, W_attnfc, W_pk
    const float* Wfc1 = w16[0];
    const float* Ww   = w16[1];
    const float* Wk   = w16[2];
    const float* Wv   = w16[3];
    const float* Wat  = w16[4];
    const float* Wpk  = w16[5];

    const int smem_main = (13312 + 13728 + 864) * (int)sizeof(float);  // 111616 B
    cudaFuncSetAttribute(decoder_main, cudaFuncAttributeMaxDynamicSharedMemorySize, smem_main);

    precomp0<<<257, 128>>>(Wfc, Ww, Wat, Wpk);
    precomp2a<<<Bq / 2, 256>>>(pool, Wfc1);
    precomp2b<<<(Bq * Tq) / 16, 256>>>(Ww);
    decoder_main<<<Bq, 256, smem_main>>>(enc, capc, dem, Wk, Wv, (float*)d_out);
}